// round 5
// baseline (speedup 1.0000x reference)
#include <cuda_runtime.h>
#include <math.h>

#define DZ 32
#define DA 16
#define KMIX 8
#define DH 64
#define DG 64
#define TT 128
#define NB 256
#define LD 36    // padded stride, 16B-aligned rows
#define LDK 20   // padded stride for K (32x16), 16B-aligned rows

// output offsets (elements), per flattened reference tuple
#define OFF_ZF  0ull
#define OFF_PF  1048576ull
#define OFF_ZP  34603008ull
#define OFF_AF  35651584ull
#define OFF_AP  36175872ull
#define OFF_PP  36700160ull
#define OFF_ALP 70254592ull
#define OFF_AL  70516736ull
#define OFF_CL  104071168ull
#define OFF_ZM  120848384ull
#define OFF_LT  121896960ull
#define OFF_S   155451392ull

// C for slot 128 (not part of CL output)
__device__ __align__(16) float g_C128[NB * 512];

__device__ __forceinline__ float sigmoidf_(float x){ return 1.0f/(1.0f+expf(-x)); }

__device__ __forceinline__ float dot32(const float* __restrict__ a, const float* __restrict__ b){
    float4 s = make_float4(0.f,0.f,0.f,0.f);
    #pragma unroll
    for (int c = 0; c < 8; c++){
        float4 x = ((const float4*)a)[c];
        float4 y = ((const float4*)b)[c];
        s.x += x.x*y.x; s.y += x.y*y.y; s.z += x.z*y.z; s.w += x.w*y.w;
    }
    return (s.x+s.y)+(s.z+s.w);
}

// ================= alpha chain kernel: GRU + softmax + mixtures =================
// Writes AL, ALP, CL outputs directly; slot-128 C to g_C128.
__global__ void alpha_kernel(const float* __restrict__ a_seq, const float* __restrict__ h_obs,
                             const float* __restrict__ a0,
                             const float* __restrict__ Amat, const float* __restrict__ Cmat,
                             const float* __restrict__ Wx,   const float* __restrict__ Wh,
                             const float* __restrict__ bb,   const float* __restrict__ Wo,
                             const float* __restrict__ bo,   float* __restrict__ out)
{
    __shared__ float xv[80], h[64], hnew[64], gx[192], gh[192], alpha[8], part[192];
    const int b = blockIdx.x, tid = threadIdx.x;

    // h_ctx = mean_t h_obs
    {
        int d = tid & 63, c = tid >> 6;
        int t0 = c*43, t1 = (c==2) ? 128 : (t0+43);
        float s = 0.f;
        const float* hp = h_obs + ((size_t)b*TT + t0)*DH + d;
        #pragma unroll 4
        for (int t = t0; t < t1; t++, hp += DH) s += *hp;
        part[tid] = s;
    }
    if (tid < 16) xv[tid] = a0[tid];
    if (tid < 64) h[tid] = 0.f;
    __syncthreads();
    if (tid < 64) xv[16+tid] = (part[tid]+part[64+tid]+part[128+tid])*(1.0f/128.0f);
    __syncthreads();

    for (int s = 0; s <= TT; s++){
        // gx = [a, hctx] @ Wx + b ; gh = h @ Wh
        {
            float g = bb[tid];
            #pragma unroll 8
            for (int i = 0; i < 80; i++) g += xv[i]*Wx[i*192 + tid];
            gx[tid] = g;
            float g2 = 0.f;
            if (s > 0){
                #pragma unroll 8
                for (int d = 0; d < 64; d++) g2 += h[d]*Wh[d*192 + tid];
            }
            gh[tid] = g2;
        }
        __syncthreads();
        if (tid < 64){
            float r = sigmoidf_(gx[tid]      + gh[tid]);
            float u = sigmoidf_(gx[64 + tid] + gh[64 + tid]);
            float n = tanhf   (gx[128 + tid] + r*gh[128 + tid]);
            hnew[tid] = (1.f - u)*n + u*h[tid];
        }
        __syncthreads();
        if (tid < 8){
            float lg = bo[tid];
            #pragma unroll 8
            for (int d = 0; d < 64; d++) lg += hnew[d]*Wo[d*KMIX + tid];
            float m = lg;
            #pragma unroll
            for (int o = 4; o; o >>= 1) m = fmaxf(m, __shfl_xor_sync(0xFF, m, o));
            float ev = expf(lg - m), sm = ev;
            #pragma unroll
            for (int o = 4; o; o >>= 1) sm += __shfl_xor_sync(0xFF, sm, o);
            float al = ev/sm;
            alpha[tid] = al;
            if (s >= 1) out[OFF_ALP + ((size_t)b*TT + (s-1))*8 + tid] = al;
        }
        if (tid >= 64 && tid < 128) h[tid-64] = hnew[tid-64];
        __syncthreads();
        // mixtures
        if (s >= 1){
            #pragma unroll
            for (int r = 0; r < 6; r++){
                int e = tid + 192*r;
                if (e < 1024){
                    float v = 0.f;
                    #pragma unroll
                    for (int k = 0; k < KMIX; k++) v += alpha[k]*Amat[k*1024 + e];
                    out[OFF_AL + ((size_t)b*TT + (s-1))*1024 + e] = v;
                }
            }
        }
        {
            #pragma unroll
            for (int r = 0; r < 3; r++){
                int e = tid + 192*r;
                if (e < 512){
                    float v = 0.f;
                    #pragma unroll
                    for (int k = 0; k < KMIX; k++) v += alpha[k]*Cmat[k*512 + e];
                    if (s <= 127) out[OFF_CL + ((size_t)b*TT + s)*512 + e] = v;
                    else          g_C128[b*512 + e] = v;
                }
            }
        }
        if (tid < 16 && s < TT) xv[tid] = a_seq[((size_t)b*TT + s)*16 + tid];
        __syncthreads();
    }
}

// ================= main Kalman kernel =================
__global__ __launch_bounds__(256, 2)
void kf_kernel(const float* __restrict__ a_seq, float* __restrict__ out)
{
    __shared__ __align__(16) float P[DZ*LD], Pf[DZ*LD], Xb[DZ*LD], M2[DZ*LD], As[DZ*LD], CH[DZ*LD];
    __shared__ __align__(16) float Cb[2][DA*LD], CP[DA*LD], SG[DA*LD];
    __shared__ __align__(16) float Kg[DZ*LDK];
    __shared__ float zn[DZ], zfn[DZ], rvec[DA];

    const int tid  = threadIdx.x;
    const int wid  = tid >> 5;
    const int lane = tid & 31;
    const int b    = blockIdx.x;

    // prologue
    if (tid < DZ) zn[tid] = 0.f;
    #pragma unroll
    for (int k = 0; k < 4; k++){
        int e = tid + 256*k;
        int i = e >> 5, j = e & 31;
        P[i*LD + j] = (i == j) ? 10.f : 0.f;
    }
    #pragma unroll
    for (int k = 0; k < 2; k++){
        int e = tid + 256*k;
        int i = e >> 5, j = e & 31;
        Cb[0][i*LD + j] = out[OFF_CL + (size_t)b*TT*512 + e];
    }
    __syncthreads();

    for (int t = 0; t < TT; t++){
        const size_t bt = (size_t)b*TT + t;
        float* Ct = Cb[t & 1];
        float* Cn = Cb[(t+1) & 1];

        if (wid < 7){
            // ---- phA: CP = C_t * P  (128 thr)  ||  prefetch A_{t+1}, C_{t+1} (96 thr)
            if (tid < 128){
                int i = tid >> 3, jt = tid & 7;
                float4 acc = make_float4(0.f,0.f,0.f,0.f);
                const float* pr = P + jt*4;
                #pragma unroll
                for (int m = 0; m < 32; m++){
                    float c = Ct[i*LD + m];
                    float4 p4 = *(const float4*)(pr + m*LD);
                    acc.x += c*p4.x; acc.y += c*p4.y; acc.z += c*p4.z; acc.w += c*p4.w;
                }
                *(float4*)&CP[i*LD + jt*4] = acc;
            } else {
                int idx = tid - 128;
                #pragma unroll
                for (int r = 0; r < 4; r++){
                    int e = r*384 + idx*4;
                    float4 g;
                    if (e < 1024){
                        g = *(const float4*)(out + OFF_AL + bt*1024 + e);
                        int i = e >> 5, j = e & 31;
                        *(float4*)&As[i*LD + j] = g;
                    } else {
                        int e2 = e - 1024;
                        if (t < 127) g = *(const float4*)(out + OFF_CL + (bt+1)*512 + e2);
                        else         g = *(const float4*)(g_C128 + b*512 + e2);
                        int i = e2 >> 5, j = e2 & 31;
                        *(float4*)&Cn[i*LD + j] = g;
                    }
                }
            }
            asm volatile("bar.sync 1, 224;" ::: "memory");

            // ---- phB: S = CP C_t^T + 0.3I (store out)  ||  rvec
            float av = 0.f;
            if (tid >= 192 && tid < 208) av = a_seq[bt*DA + (tid-192)];
            {
                int e = tid;
                int i = e >> 4, j = e & 15;
                float s = ((i == j) ? 0.3f : 0.f) + dot32(CP + i*LD, Ct + j*LD);
                SG[i*LD + j] = s;
                out[OFF_S + bt*256 + e] = s;
            }
            if (tid < 32){
                int e = 224 + tid;
                int i = e >> 4, j = e & 15;
                float s = ((i == j) ? 0.3f : 0.f) + dot32(CP + i*LD, Ct + j*LD);
                SG[i*LD + j] = s;
                out[OFF_S + bt*256 + e] = s;
            }
            if (tid >= 192 && tid < 208){
                int la = tid - 192;
                rvec[la] = av - dot32(Ct + la*LD, zn);
            }
            __syncthreads();   // endB: warp7 takes S

            // ---- phC: deferred stores of step t-1 (warp7 does GJ)
            if (t > 0){
                const size_t btp = bt - 1;
                #pragma unroll
                for (int k = 0; k < 5; k++){
                    int e = tid + 224*k;
                    if (e < 1024){
                        int i = e >> 5, j = e & 31;
                        out[OFF_PF + btp*1024 + e] = Pf[i*LD + j];
                        out[OFF_PP + btp*1024 + e] = P[i*LD + j];
                        float l;
                        if (j < i)       l = CH[i*LD + j]*rsqrtf(CH[j*LD + j]);
                        else if (j == i) l = sqrtf(CH[i*LD + i]);
                        else             l = 0.f;
                        out[OFF_LT + btp*1024 + e] = l;
                    }
                }
            }
            __syncthreads();   // endC: Sinv ready

            // ---- phD: K = (CP)^T * Sinv  (128 thr)
            if (tid < 128){
                int i = tid >> 2, jt = tid & 3;
                float4 acc = make_float4(0.f,0.f,0.f,0.f);
                #pragma unroll
                for (int m = 0; m < 16; m++){
                    float c = CP[m*LD + i];
                    float4 s4 = *(const float4*)&SG[m*LD + 16 + jt*4];
                    acc.x += c*s4.x; acc.y += c*s4.y; acc.z += c*s4.z; acc.w += c*s4.w;
                }
                *(float4*)&Kg[i*LDK + jt*4] = acc;
            }
            asm volatile("bar.sync 1, 224;" ::: "memory");

            // ---- phE: X = K * CP  ;  zfn = zn + K rvec
            {
                #pragma unroll
                for (int q = 0; q < 2; q++){
                    int T = (q == 0) ? tid : (224 + tid);
                    if (q == 1 && tid >= 32) break;
                    int i = T >> 3, jt = T & 7;
                    float4 acc = make_float4(0.f,0.f,0.f,0.f);
                    #pragma unroll
                    for (int m = 0; m < 16; m++){
                        float kv = Kg[i*LDK + m];
                        float4 c4 = *(const float4*)&CP[m*LD + jt*4];
                        acc.x += kv*c4.x; acc.y += kv*c4.y; acc.z += kv*c4.z; acc.w += kv*c4.w;
                    }
                    *(float4*)&Xb[i*LD + jt*4] = acc;
                }
            }
            if (tid >= 192){
                int la = tid - 192;
                float s = zn[la];
                #pragma unroll
                for (int m = 0; m < 16; m++) s += Kg[la*LDK + m]*rvec[m];
                zfn[la] = s;
            }
            asm volatile("bar.sync 1, 224;" ::: "memory");

            // ---- phF: Pf = P - 0.5(X + X^T); CH = Pf + jitter; zp/afl/vec stores
            {
                #pragma unroll
                for (int q = 0; q < 2; q++){
                    int T = (q == 0) ? tid : (224 + tid);
                    if (q == 1 && tid >= 32) break;
                    int i = T >> 3, jt = T & 7;
                    float4 p4 = *(const float4*)&P[i*LD + jt*4];
                    float4 x4 = *(const float4*)&Xb[i*LD + jt*4];
                    float4 xt;
                    xt.x = Xb[(jt*4+0)*LD + i];
                    xt.y = Xb[(jt*4+1)*LD + i];
                    xt.z = Xb[(jt*4+2)*LD + i];
                    xt.w = Xb[(jt*4+3)*LD + i];
                    float4 pf4;
                    pf4.x = p4.x - 0.5f*(x4.x + xt.x);
                    pf4.y = p4.y - 0.5f*(x4.y + xt.y);
                    pf4.z = p4.z - 0.5f*(x4.z + xt.z);
                    pf4.w = p4.w - 0.5f*(x4.w + xt.w);
                    *(float4*)&Pf[i*LD + jt*4] = pf4;
                    float4 ch4 = pf4;
                    if (jt*4+0 == i) ch4.x += 2e-4f;
                    if (jt*4+1 == i) ch4.y += 2e-4f;
                    if (jt*4+2 == i) ch4.z += 2e-4f;
                    if (jt*4+3 == i) ch4.w += 2e-4f;
                    *(float4*)&CH[i*LD + jt*4] = ch4;
                }
            }
            if (tid >= 160 && tid < 192){
                int la = tid - 160;
                float zpv = dot32(As + la*LD, zfn);
                zn[la] = zpv;   // carry: znew_{t+1} = z_pred_t
                out[OFF_ZP + bt*32 + la] = zpv;
            } else if (tid >= 128 && tid < 144){
                int la = tid - 128;
                out[OFF_AF + bt*16 + la] = dot32(Ct + la*LD, zfn);
            } else if (tid >= 96 && tid < 128){
                int la = tid - 96;
                float z = zfn[la];
                out[OFF_ZF + bt*32 + la] = z;
                out[OFF_ZM + bt*32 + la] = z;
            }
            __syncthreads();   // endF: CH ready for warp7 Cholesky

            // ---- phG: M2 = A_{t+1} * Pf
            {
                #pragma unroll
                for (int q = 0; q < 2; q++){
                    int T = (q == 0) ? tid : (224 + tid);
                    if (q == 1 && tid >= 32) break;
                    int i = T >> 3, jt = T & 7;
                    float4 acc = make_float4(0.f,0.f,0.f,0.f);
                    const float* pr = Pf + jt*4;
                    #pragma unroll
                    for (int m = 0; m < 32; m++){
                        float a = As[i*LD + m];
                        float4 p4 = *(const float4*)(pr + m*LD);
                        acc.x += a*p4.x; acc.y += a*p4.y; acc.z += a*p4.z; acc.w += a*p4.w;
                    }
                    *(float4*)&M2[i*LD + jt*4] = acc;
                }
            }
            asm volatile("bar.sync 1, 224;" ::: "memory");

            // ---- phH: RAW = M2 * A^T (into Xb) ; ap
            {
                #pragma unroll
                for (int k = 0; k < 5; k++){
                    int e = tid + 224*k;
                    if (e < 1024){
                        int i = e >> 5, j = e & 31;
                        Xb[i*LD + j] = dot32(M2 + i*LD, As + j*LD);
                    }
                }
            }
            if (tid >= 128 && tid < 144){
                int la = tid - 128;
                out[OFF_AP + bt*16 + la] = dot32(Cn + la*LD, zn);
            }
            asm volatile("bar.sync 1, 224;" ::: "memory");

            // ---- phI: P = sym(RAW) + Q (carry)
            {
                #pragma unroll
                for (int k = 0; k < 5; k++){
                    int e = tid + 224*k;
                    if (e < 1024){
                        int i = e >> 5, j = e & 31;
                        P[i*LD + j] = 0.5f*(Xb[i*LD + j] + Xb[j*LD + i]) + ((i == j) ? 0.2f : 0.f);
                    }
                }
            }
            asm volatile("bar.sync 1, 224;" ::: "memory");
        } else {
            // ================= warp 7: serial specialist =================
            __syncthreads();   // endB: S ready
            // GJ inversion of S (registers + shuffle)
            {
                float c[16];
                #pragma unroll
                for (int i = 0; i < 16; i++)
                    c[i] = (lane < 16) ? SG[i*LD + lane] : ((i == lane-16) ? 1.f : 0.f);
                #pragma unroll
                for (int p = 0; p < 16; p++){
                    float spp = __shfl_sync(0xffffffffu, c[p], p);
                    float inv = 1.0f/spp;
                    float pivj = c[p]*inv;
                    #pragma unroll
                    for (int i = 0; i < 16; i++){
                        float fac = __shfl_sync(0xffffffffu, c[i], p);
                        if (i != p) c[i] -= fac*pivj;
                    }
                    c[p] = pivj;
                }
                if (lane >= 16){
                    #pragma unroll
                    for (int i = 0; i < 16; i++) SG[i*LD + lane] = c[i];
                }
            }
            __syncthreads();   // endC: hand Sinv to warps 0-6
            __syncthreads();   // endF: CH ready
            // Cholesky trailing update on CH (overlaps phG..next phB)
            for (int j = 0; j < DZ-1; j++){
                float inv = __fdividef(1.0f, CH[j*LD + j]);
                int kk = j + 1 + lane;
                if (kk < DZ){
                    float ckj = CH[kk*LD + j]*inv;
                    for (int ii = kk; ii < DZ; ii++)
                        CH[ii*LD + kk] -= CH[ii*LD + j]*ckj;
                }
                __syncwarp();
            }
        }
    }

    // epilogue: stores for t = 127
    __syncthreads();
    {
        const size_t btl = (size_t)b*TT + 127;
        #pragma unroll
        for (int k = 0; k < 4; k++){
            int e = tid + 256*k;
            int i = e >> 5, j = e & 31;
            out[OFF_PF + btl*1024 + e] = Pf[i*LD + j];
            out[OFF_PP + btl*1024 + e] = P[i*LD + j];
            float l;
            if (j < i)       l = CH[i*LD + j]*rsqrtf(CH[j*LD + j]);
            else if (j == i) l = sqrtf(CH[i*LD + i]);
            else             l = 0.f;
            out[OFF_LT + btl*1024 + e] = l;
        }
    }
}

extern "C" void kernel_launch(void* const* d_in, const int* in_sizes, int n_in,
                              void* d_out, int out_size) {
    const float* a_seq = (const float*)d_in[0];
    const float* h_obs = (const float*)d_in[1];
    const float* Amat  = (const float*)d_in[2];
    const float* Cmat  = (const float*)d_in[3];
    const float* a0    = (const float*)d_in[4];
    const float* Wx    = (const float*)d_in[5];
    const float* Wh    = (const float*)d_in[6];
    const float* bb    = (const float*)d_in[7];
    const float* Wo    = (const float*)d_in[8];
    const float* bo    = (const float*)d_in[9];
    float* out = (float*)d_out;

    alpha_kernel<<<NB, 192>>>(a_seq, h_obs, a0, Amat, Cmat, Wx, Wh, bb, Wo, bo, out);
    kf_kernel<<<NB, 256>>>(a_seq, out);
}

// round 6
// speedup vs baseline: 1.1790x; 1.1790x over previous
#include <cuda_runtime.h>
#include <math.h>

#define TT 128
#define NB 256
#define OFF_ZF  0ull
#define OFF_PF  1048576ull
#define OFF_ZP  34603008ull
#define OFF_AF  35651584ull
#define OFF_AP  36175872ull
#define OFF_PP  36700160ull
#define OFF_ALP 70254592ull
#define OFF_AL  70516736ull
#define OFF_CL  104071168ull
#define OFF_ZM  120848384ull
#define OFF_LT  121896960ull
#define OFF_S   155451392ull

__device__ float g_alpha[(size_t)NB * 129 * 8];
__device__ __align__(16) float g_C128[NB * 512];

__device__ __forceinline__ float sigmoidf_(float x){ return 1.0f/(1.0f+expf(-x)); }

__device__ __forceinline__ float dot32(const float* __restrict__ a, const float* __restrict__ b){
    float4 s = make_float4(0.f,0.f,0.f,0.f);
    #pragma unroll
    for (int c = 0; c < 8; c++){
        float4 x = ((const float4*)a)[c];
        float4 y = ((const float4*)b)[c];
        s.x += x.x*y.x; s.y += x.y*y.y; s.z += x.z*y.z; s.w += x.w*y.w;
    }
    return (s.x+s.y)+(s.z+s.w);
}

// ============ serial GRU chain: alphas only (register weights) ============
__global__ __launch_bounds__(192)
void gru_kernel(const float* __restrict__ a_seq, const float* __restrict__ h_obs,
                const float* __restrict__ a0,    const float* __restrict__ Wx,
                const float* __restrict__ Wh,    const float* __restrict__ bb,
                const float* __restrict__ Wo,    const float* __restrict__ bo,
                float* __restrict__ out)
{
    __shared__ float av[16], hs[64], hn[64], gx[192], gh[192], hx[64], part[192];
    const int b = blockIdx.x, tid = threadIdx.x;
    {
        int c = tid >> 6, d = tid & 63;
        int t0 = c*43, t1 = (c==2) ? 128 : (t0+43);
        float s = 0.f;
        const float* hp = h_obs + ((size_t)b*TT + t0)*64 + d;
        for (int t = t0; t < t1; t++, hp += 64) s += *hp;
        part[tid] = s;
    }
    if (tid < 16) av[tid] = a0[tid];
    if (tid < 64) hs[tid] = 0.f;
    __syncthreads();
    if (tid < 64) hx[tid] = (part[tid]+part[64+tid]+part[128+tid])*(1.0f/128.0f);
    __syncthreads();
    float wxr[16], whr[64];
    #pragma unroll
    for (int i = 0; i < 16; i++) wxr[i] = Wx[i*192 + tid];
    #pragma unroll 8
    for (int d = 0; d < 64; d++) whr[d] = Wh[d*192 + tid];
    float gst = bb[tid];
    #pragma unroll 8
    for (int d = 0; d < 64; d++) gst += hx[d]*Wx[(16+d)*192 + tid];

    for (int s = 0; s <= TT; s++){
        float g = gst;
        #pragma unroll
        for (int i = 0; i < 16; i++) g += av[i]*wxr[i];
        gx[tid] = g;
        float g2 = 0.f;
        #pragma unroll 8
        for (int d = 0; d < 64; d++) g2 += hs[d]*whr[d];
        gh[tid] = g2;
        __syncthreads();
        if (tid < 64){
            float r = sigmoidf_(gx[tid]       + gh[tid]);
            float u = sigmoidf_(gx[64 + tid]  + gh[64 + tid]);
            float n = tanhf   (gx[128 + tid] + r*gh[128 + tid]);
            hn[tid] = (1.f - u)*n + u*hs[tid];
        } else if (tid >= 176 && s < TT){
            av[tid-176] = a_seq[((size_t)b*TT + s)*16 + (tid-176)];
        }
        __syncthreads();
        if (tid >= 64 && tid < 128) hs[tid-64] = hn[tid-64];
        if (tid < 8){
            float lg = bo[tid];
            #pragma unroll 8
            for (int d = 0; d < 64; d++) lg += hn[d]*Wo[d*8 + tid];
            float m = lg;
            #pragma unroll
            for (int o = 4; o; o >>= 1) m = fmaxf(m, __shfl_xor_sync(0xFF, m, o));
            float ev = expf(lg - m), sm = ev;
            #pragma unroll
            for (int o = 4; o; o >>= 1) sm += __shfl_xor_sync(0xFF, sm, o);
            float al = ev/sm;
            g_alpha[((size_t)b*129 + s)*8 + tid] = al;
            if (s >= 1) out[OFF_ALP + ((size_t)b*TT + (s-1))*8 + tid] = al;
        }
        __syncthreads();
    }
}

// ============ parallel mixtures: AL/CL from alphas ============
__global__ __launch_bounds__(192)
void mix_kernel(const float* __restrict__ Amat, const float* __restrict__ Cmat,
                float* __restrict__ out)
{
    const int b = blockIdx.x, s = blockIdx.y, tid = threadIdx.x;
    __shared__ float al[8];
    if (tid < 8) al[tid] = g_alpha[((size_t)b*129 + s)*8 + tid];
    __syncthreads();
    if (s >= 1){
        #pragma unroll
        for (int r = 0; r < 6; r++){
            int e = tid + 192*r;
            if (e < 1024){
                float v = 0.f;
                #pragma unroll
                for (int k = 0; k < 8; k++) v += al[k]*Amat[k*1024 + e];
                out[OFF_AL + ((size_t)b*TT + (s-1))*1024 + e] = v;
            }
        }
    }
    #pragma unroll
    for (int r = 0; r < 3; r++){
        int e = tid + 192*r;
        if (e < 512){
            float v = 0.f;
            #pragma unroll
            for (int k = 0; k < 8; k++) v += al[k]*Cmat[k*512 + e];
            if (s <= 127) out[OFF_CL + ((size_t)b*TT + s)*512 + e] = v;
            else          g_C128[b*512 + e] = v;
        }
    }
}

// ============ main Kalman kernel ============
__global__ __launch_bounds__(256, 2)
void kf_kernel(const float* __restrict__ a_seq, float* __restrict__ out)
{
    __shared__ __align__(16) float P[1152], Pf[1152], Xb[1152], As[1152], AsT[1152], CH[1152];
    __shared__ __align__(16) float Cb[2][576], CtT[2][640], CP[576], Wb[576], SG[320];
    __shared__ float zn[32], zfn[32], rvec[16], srv[16];

    const int tid = threadIdx.x, wid = tid >> 5, lane = tid & 31;
    const int b = blockIdx.x;

    if (tid < 32) zn[tid] = 0.f;
    #pragma unroll
    for (int k = 0; k < 4; k++){
        int e = tid + 256*k, i = e >> 5, j = e & 31;
        P[i*36 + j] = (i == j) ? 10.f : 0.f;
    }
    if (tid < 128){
        int e = tid*4, i = e >> 5, j = e & 31;
        float4 g = *(const float4*)(out + OFF_CL + (size_t)b*TT*512 + e);
        *(float4*)&Cb[0][i*36 + j] = g;
        CtT[0][(j+0)*20+i] = g.x; CtT[0][(j+1)*20+i] = g.y;
        CtT[0][(j+2)*20+i] = g.z; CtT[0][(j+3)*20+i] = g.w;
    }
    __syncthreads();

    for (int t = 0; t < TT; t++){
        const size_t bt = (size_t)b*TT + t;
        float* Ct  = Cb[t & 1];
        float* Cn  = Cb[(t+1) & 1];
        float* CtTc = CtT[t & 1];
        float* CtTn = CtT[(t+1) & 1];

        if (wid < 7){
            // phA: CP = C_t * P (128 thr) || prefetch A_{t+1}, C_{t+1} (+transposes)
            if (tid < 128){
                int i = tid >> 3, j4 = (tid & 7)*4;
                float4 acc = make_float4(0.f,0.f,0.f,0.f);
                #pragma unroll 8
                for (int m = 0; m < 32; m++){
                    float c = Ct[i*36 + m];
                    float4 p4 = *(const float4*)(P + m*36 + j4);
                    acc.x += c*p4.x; acc.y += c*p4.y; acc.z += c*p4.z; acc.w += c*p4.w;
                }
                *(float4*)&CP[i*36 + j4] = acc;
            } else {
                int idx = tid - 128;
                #pragma unroll
                for (int r = 0; r < 4; r++){
                    int e = r*384 + idx*4;
                    if (e < 1024){
                        float4 g = *(const float4*)(out + OFF_AL + bt*1024 + e);
                        int i = e >> 5, j = e & 31;
                        *(float4*)&As[i*36 + j] = g;
                        AsT[(j+0)*36+i] = g.x; AsT[(j+1)*36+i] = g.y;
                        AsT[(j+2)*36+i] = g.z; AsT[(j+3)*36+i] = g.w;
                    } else {
                        int e2 = e - 1024;
                        float4 g = (t < 127) ? *(const float4*)(out + OFF_CL + (bt+1)*512 + e2)
                                             : *(const float4*)(g_C128 + b*512 + e2);
                        int i = e2 >> 5, j = e2 & 31;
                        *(float4*)&Cn[i*36 + j] = g;
                        CtTn[(j+0)*20+i] = g.x; CtTn[(j+1)*20+i] = g.y;
                        CtTn[(j+2)*20+i] = g.z; CtTn[(j+3)*20+i] = g.w;
                    }
                }
            }
            asm volatile("bar.sync 1, 224;" ::: "memory");

            // phB: S = CP*Ct^T + 0.3I (broadcast via CtT) ; rvec
            if (tid < 64){
                int i = tid >> 2, j4 = (tid & 3)*4;
                float4 acc = make_float4(0.f,0.f,0.f,0.f);
                #pragma unroll 8
                for (int m = 0; m < 32; m++){
                    float cp = CP[i*36 + m];
                    float4 c4 = *(const float4*)(CtTc + m*20 + j4);
                    acc.x += cp*c4.x; acc.y += cp*c4.y; acc.z += cp*c4.z; acc.w += cp*c4.w;
                }
                if (j4+0 == i) acc.x += 0.3f;
                if (j4+1 == i) acc.y += 0.3f;
                if (j4+2 == i) acc.z += 0.3f;
                if (j4+3 == i) acc.w += 0.3f;
                *(float4*)&SG[i*20 + j4] = acc;
                *(float4*)(out + OFF_S + bt*256 + i*16 + j4) = acc;
            } else if (tid < 80){
                int la = tid - 64;
                float av = a_seq[bt*16 + la];
                float s = 0.f;
                #pragma unroll 8
                for (int m = 0; m < 32; m++) s += Ct[la*36 + m]*zn[m];
                rvec[la] = av - s;
            }
            __syncthreads();   // endB

            // phC: deferred stores of t-1 (warp7 does GJ)
            if (t > 0){
                const size_t bp = bt - 1;
                #pragma unroll
                for (int k = 0; k < 5; k++){
                    int e = tid + 224*k;
                    if (e < 1024){
                        int i = e >> 5, j = e & 31;
                        out[OFF_PF + bp*1024 + e] = Pf[i*36 + j];
                        out[OFF_PP + bp*1024 + e] = P[i*36 + j];
                        float l;
                        if (j < i)       l = CH[i*36 + j]*rsqrtf(CH[j*36 + j]);
                        else if (j == i) l = sqrtf(CH[i*36 + i]);
                        else             l = 0.f;
                        out[OFF_LT + bp*1024 + e] = l;
                    }
                }
            }
            __syncthreads();   // endC: W, sr ready

            // phE: X = CP^T * W ; zfn
            #pragma unroll
            for (int q = 0; q < 2; q++){
                int T = (q == 0) ? tid : (224 + tid);
                if (q == 1 && tid >= 32) break;
                int i = T >> 3, j4 = (T & 7)*4;
                float4 acc = make_float4(0.f,0.f,0.f,0.f);
                #pragma unroll
                for (int m = 0; m < 16; m++){
                    float cp = CP[m*36 + i];
                    float4 w4 = *(const float4*)(Wb + m*36 + j4);
                    acc.x += cp*w4.x; acc.y += cp*w4.y; acc.z += cp*w4.z; acc.w += cp*w4.w;
                }
                *(float4*)&Xb[i*36 + j4] = acc;
            }
            if (tid < 32){
                float s = zn[tid];
                #pragma unroll
                for (int m = 0; m < 16; m++) s += CP[m*36 + tid]*srv[m];
                zfn[tid] = s;
            }
            asm volatile("bar.sync 1, 224;" ::: "memory");

            // phF: Pf = P - 0.5(X+X^T); CH = Pf + jitter; vec outputs
            #pragma unroll
            for (int q = 0; q < 2; q++){
                int T = (q == 0) ? tid : (224 + tid);
                if (q == 1 && tid >= 32) break;
                int i = T >> 3, j4 = (T & 7)*4;
                float4 p4 = *(const float4*)&P[i*36 + j4];
                float4 x4 = *(const float4*)&Xb[i*36 + j4];
                float4 pf4;
                pf4.x = p4.x - 0.5f*(x4.x + Xb[(j4+0)*36 + i]);
                pf4.y = p4.y - 0.5f*(x4.y + Xb[(j4+1)*36 + i]);
                pf4.z = p4.z - 0.5f*(x4.z + Xb[(j4+2)*36 + i]);
                pf4.w = p4.w - 0.5f*(x4.w + Xb[(j4+3)*36 + i]);
                *(float4*)&Pf[i*36 + j4] = pf4;
                if (j4+0 == i) pf4.x += 2e-4f;
                if (j4+1 == i) pf4.y += 2e-4f;
                if (j4+2 == i) pf4.z += 2e-4f;
                if (j4+3 == i) pf4.w += 2e-4f;
                *(float4*)&CH[i*36 + j4] = pf4;
            }
            if (tid >= 160 && tid < 192){
                int la = tid - 160;
                float zp = dot32(As + la*36, zfn);
                zn[la] = zp;
                out[OFF_ZP + bt*32 + la] = zp;
            } else if (tid >= 144 && tid < 160){
                int la = tid - 144;
                out[OFF_AF + bt*16 + la] = dot32(Ct + la*36, zfn);
            } else if (tid >= 96 && tid < 128){
                int la = tid - 96;
                float z = zfn[la];
                out[OFF_ZF + bt*32 + la] = z;
                out[OFF_ZM + bt*32 + la] = z;
            }
            __syncthreads();   // endF: CH to warp7

            // phG: M2 = A_{t+1} * Pf  (into Xb)
            #pragma unroll
            for (int q = 0; q < 2; q++){
                int T = (q == 0) ? tid : (224 + tid);
                if (q == 1 && tid >= 32) break;
                int i = T >> 3, j4 = (T & 7)*4;
                float4 acc = make_float4(0.f,0.f,0.f,0.f);
                #pragma unroll 8
                for (int m = 0; m < 32; m++){
                    float a = As[i*36 + m];
                    float4 p4 = *(const float4*)(Pf + m*36 + j4);
                    acc.x += a*p4.x; acc.y += a*p4.y; acc.z += a*p4.z; acc.w += a*p4.w;
                }
                *(float4*)&Xb[i*36 + j4] = acc;
            }
            asm volatile("bar.sync 1, 224;" ::: "memory");

            // phH: RAW = M2 * A^T (broadcast via AsT, into As) ; ap
            #pragma unroll
            for (int q = 0; q < 2; q++){
                int T = (q == 0) ? tid : (224 + tid);
                if (q == 1 && tid >= 32) break;
                int i = T >> 3, j4 = (T & 7)*4;
                float4 acc = make_float4(0.f,0.f,0.f,0.f);
                #pragma unroll 8
                for (int m = 0; m < 32; m++){
                    float v = Xb[i*36 + m];
                    float4 a4 = *(const float4*)(AsT + m*36 + j4);
                    acc.x += v*a4.x; acc.y += v*a4.y; acc.z += v*a4.z; acc.w += v*a4.w;
                }
                *(float4*)&As[i*36 + j4] = acc;
            }
            if (tid >= 128 && tid < 144){
                int la = tid - 128;
                out[OFF_AP + bt*16 + la] = dot32(Cn + la*36, zn);
            }
            asm volatile("bar.sync 1, 224;" ::: "memory");

            // phI: P = sym(RAW) + Q
            #pragma unroll
            for (int k = 0; k < 5; k++){
                int e = tid + 224*k;
                if (e < 1024){
                    int i = e >> 5, j = e & 31;
                    P[i*36 + j] = 0.5f*(As[i*36 + j] + As[j*36 + i]) + ((i == j) ? 0.2f : 0.f);
                }
            }
            asm volatile("bar.sync 1, 224;" ::: "memory");
        } else {
            // ===== warp 7: serial specialist =====
            __syncthreads();   // endB
            {
                // augmented GJ on [S | r | CP] -> W = Sinv*CP, srv = Sinv*r
                float c[16], d[16];
                #pragma unroll
                for (int i = 0; i < 16; i++){
                    c[i] = (lane < 16) ? SG[i*20 + lane] : ((lane == 16) ? rvec[i] : 0.f);
                    d[i] = CP[i*36 + lane];
                }
                #pragma unroll
                for (int p = 0; p < 16; p++){
                    float piv = __shfl_sync(0xffffffffu, c[p], p);
                    float inv = 1.0f/piv;
                    float pc = c[p]*inv, pd = d[p]*inv;
                    #pragma unroll
                    for (int i = 0; i < 16; i++){
                        if (i == p) continue;
                        float fc = __shfl_sync(0xffffffffu, c[i], p);
                        c[i] -= fc*pc; d[i] -= fc*pd;
                    }
                    c[p] = pc; d[p] = pd;
                }
                #pragma unroll
                for (int i = 0; i < 16; i++) Wb[i*36 + lane] = d[i];
                if (lane == 16){
                    #pragma unroll
                    for (int i = 0; i < 16; i++) srv[i] = c[i];
                }
            }
            __syncthreads();   // endC
            __syncthreads();   // endF
            // Cholesky trailing update on CH (overlaps phG..next phB)
            for (int j = 0; j < 31; j++){
                float inv = __fdividef(1.0f, CH[j*36 + j]);
                int kk = j + 1 + lane;
                if (kk < 32){
                    float ckj = CH[kk*36 + j]*inv;
                    for (int ii = kk; ii < 32; ii++)
                        CH[ii*36 + kk] -= CH[ii*36 + j]*ckj;
                }
                __syncwarp();
            }
        }
    }

    // epilogue: t = 127 stores
    __syncthreads();
    const size_t bl = (size_t)b*TT + 127;
    #pragma unroll
    for (int k = 0; k < 4; k++){
        int e = tid + 256*k, i = e >> 5, j = e & 31;
        out[OFF_PF + bl*1024 + e] = Pf[i*36 + j];
        out[OFF_PP + bl*1024 + e] = P[i*36 + j];
        float l;
        if (j < i)       l = CH[i*36 + j]*rsqrtf(CH[j*36 + j]);
        else if (j == i) l = sqrtf(CH[i*36 + i]);
        else             l = 0.f;
        out[OFF_LT + bl*1024 + e] = l;
    }
}

extern "C" void kernel_launch(void* const* d_in, const int* in_sizes, int n_in,
                              void* d_out, int out_size) {
    const float* a_seq = (const float*)d_in[0];
    const float* h_obs = (const float*)d_in[1];
    const float* Amat  = (const float*)d_in[2];
    const float* Cmat  = (const float*)d_in[3];
    const float* a0    = (const float*)d_in[4];
    const float* Wx    = (const float*)d_in[5];
    const float* Wh    = (const float*)d_in[6];
    const float* bb    = (const float*)d_in[7];
    const float* Wo    = (const float*)d_in[8];
    const float* bo    = (const float*)d_in[9];
    float* out = (float*)d_out;

    gru_kernel<<<NB, 192>>>(a_seq, h_obs, a0, Wx, Wh, bb, Wo, bo, out);
    mix_kernel<<<dim3(NB, 129), 192>>>(Amat, Cmat, out);
    kf_kernel<<<NB, 256>>>(a_seq, out);
}

// round 7
// speedup vs baseline: 3.0372x; 2.5761x over previous
#include <cuda_runtime.h>
#include <math.h>

#define TT 128
#define NB 256
#define OFF_ZF  0ull
#define OFF_PF  1048576ull
#define OFF_ZP  34603008ull
#define OFF_AF  35651584ull
#define OFF_AP  36175872ull
#define OFF_PP  36700160ull
#define OFF_ALP 70254592ull
#define OFF_AL  70516736ull
#define OFF_CL  104071168ull
#define OFF_ZM  120848384ull
#define OFF_LT  121896960ull
#define OFF_S   155451392ull

#define BAR1 asm volatile("bar.sync 1, 192;" ::: "memory")
#define BAR2 asm volatile("bar.sync 2, 224;" ::: "memory")
#define BAR3 asm volatile("bar.sync 3, 224;" ::: "memory")

__device__ float g_alpha[(size_t)NB * 129 * 8];
__device__ __align__(16) float g_C128[NB * 512];

__device__ __forceinline__ float sigmoidf_(float x){ return 1.0f/(1.0f+expf(-x)); }

__device__ __forceinline__ float dot32(const float* __restrict__ a, const float* __restrict__ b){
    float4 s0 = make_float4(0.f,0.f,0.f,0.f), s1 = s0;
    #pragma unroll
    for (int c = 0; c < 4; c++){
        float4 x0 = ((const float4*)a)[c],   y0 = ((const float4*)b)[c];
        float4 x1 = ((const float4*)a)[c+4], y1 = ((const float4*)b)[c+4];
        s0.x += x0.x*y0.x; s0.y += x0.y*y0.y; s0.z += x0.z*y0.z; s0.w += x0.w*y0.w;
        s1.x += x1.x*y1.x; s1.y += x1.y*y1.y; s1.z += x1.z*y1.z; s1.w += x1.w*y1.w;
    }
    return ((s0.x+s0.y)+(s0.z+s0.w)) + ((s1.x+s1.y)+(s1.z+s1.w));
}

// map n in [0,144) -> lower-triangular float4 block (i, jb) of a 32x32 matrix
__device__ __forceinline__ void low_map(int n, int& i, int& j4){
    int q = (int)((sqrtf(1.0f + 2.0f*(float)n) - 1.0f)*0.5f);
    while (2*(q+1)*(q+2) <= n) q++;
    while (2*q*(q+1) > n) q--;
    int m0 = n - 2*q*(q+1), g = q + 1;
    int rr = m0 / g;
    i = 4*q + rr;
    j4 = (m0 - rr*g)*4;
}

// ============ serial GRU chain: alphas only ============
__global__ __launch_bounds__(192)
void gru_kernel(const float* __restrict__ a_seq, const float* __restrict__ h_obs,
                const float* __restrict__ a0,    const float* __restrict__ Wx,
                const float* __restrict__ Wh,    const float* __restrict__ bb,
                const float* __restrict__ Wo,    const float* __restrict__ bo,
                float* __restrict__ out)
{
    __shared__ float av[16], hs[64], hn[64], gx[192], gh[192], hx[64], part[192];
    const int b = blockIdx.x, tid = threadIdx.x;
    {
        int c = tid >> 6, d = tid & 63;
        int t0 = c*43, t1 = (c==2) ? 128 : (t0+43);
        float s = 0.f;
        const float* hp = h_obs + ((size_t)b*TT + t0)*64 + d;
        for (int t = t0; t < t1; t++, hp += 64) s += *hp;
        part[tid] = s;
    }
    if (tid < 16) av[tid] = a0[tid];
    if (tid < 64) hs[tid] = 0.f;
    __syncthreads();
    if (tid < 64) hx[tid] = (part[tid]+part[64+tid]+part[128+tid])*(1.0f/128.0f);
    __syncthreads();
    float wxr[16], whr[64];
    #pragma unroll
    for (int i = 0; i < 16; i++) wxr[i] = Wx[i*192 + tid];
    #pragma unroll
    for (int d = 0; d < 64; d++) whr[d] = Wh[d*192 + tid];
    float gst = bb[tid];
    {
        float s0=0.f,s1=0.f,s2=0.f,s3=0.f;
        #pragma unroll
        for (int d = 0; d < 64; d += 4){
            s0 += hx[d]*Wx[(16+d)*192 + tid];   s1 += hx[d+1]*Wx[(17+d)*192 + tid];
            s2 += hx[d+2]*Wx[(18+d)*192 + tid]; s3 += hx[d+3]*Wx[(19+d)*192 + tid];
        }
        gst += (s0+s1)+(s2+s3);
    }

    for (int s = 0; s <= TT; s++){
        {
            float ga = gst, gb2 = 0.f;
            #pragma unroll
            for (int i = 0; i < 16; i += 2){ ga += av[i]*wxr[i]; gb2 += av[i+1]*wxr[i+1]; }
            gx[tid] = ga + gb2;
            float s0=0.f,s1=0.f,s2=0.f,s3=0.f;
            #pragma unroll
            for (int d = 0; d < 64; d += 4){
                s0 += hs[d]*whr[d];     s1 += hs[d+1]*whr[d+1];
                s2 += hs[d+2]*whr[d+2]; s3 += hs[d+3]*whr[d+3];
            }
            gh[tid] = (s0+s1)+(s2+s3);
        }
        __syncthreads();
        if (tid < 64){
            float r = sigmoidf_(gx[tid]       + gh[tid]);
            float u = sigmoidf_(gx[64 + tid]  + gh[64 + tid]);
            float n = tanhf   (gx[128 + tid] + r*gh[128 + tid]);
            hn[tid] = (1.f - u)*n + u*hs[tid];
        } else if (tid >= 176 && s < TT){
            av[tid-176] = a_seq[((size_t)b*TT + s)*16 + (tid-176)];
        }
        __syncthreads();
        if (tid >= 64 && tid < 128) hs[tid-64] = hn[tid-64];
        if (tid < 8){
            float l0 = bo[tid], l1=0.f, l2=0.f, l3=0.f;
            #pragma unroll
            for (int d = 0; d < 64; d += 4){
                l0 += hn[d]*Wo[d*8 + tid];     l1 += hn[d+1]*Wo[(d+1)*8 + tid];
                l2 += hn[d+2]*Wo[(d+2)*8 + tid]; l3 += hn[d+3]*Wo[(d+3)*8 + tid];
            }
            float lg = (l0+l1)+(l2+l3);
            float m = lg;
            #pragma unroll
            for (int o = 4; o; o >>= 1) m = fmaxf(m, __shfl_xor_sync(0xFF, m, o));
            float ev = expf(lg - m), sm = ev;
            #pragma unroll
            for (int o = 4; o; o >>= 1) sm += __shfl_xor_sync(0xFF, sm, o);
            float al = ev/sm;
            g_alpha[((size_t)b*129 + s)*8 + tid] = al;
            if (s >= 1) out[OFF_ALP + ((size_t)b*TT + (s-1))*8 + tid] = al;
        }
        __syncthreads();
    }
}

// ============ parallel mixtures ============
__global__ __launch_bounds__(192)
void mix_kernel(const float* __restrict__ Amat, const float* __restrict__ Cmat,
                float* __restrict__ out)
{
    const int b = blockIdx.x, s = blockIdx.y, tid = threadIdx.x;
    __shared__ float al[8];
    if (tid < 8) al[tid] = g_alpha[((size_t)b*129 + s)*8 + tid];
    __syncthreads();
    if (s >= 1){
        #pragma unroll
        for (int r = 0; r < 6; r++){
            int e = tid + 192*r;
            if (e < 1024){
                float v = 0.f;
                #pragma unroll
                for (int k = 0; k < 8; k++) v += al[k]*Amat[k*1024 + e];
                out[OFF_AL + ((size_t)b*TT + (s-1))*1024 + e] = v;
            }
        }
    }
    #pragma unroll
    for (int r = 0; r < 3; r++){
        int e = tid + 192*r;
        if (e < 512){
            float v = 0.f;
            #pragma unroll
            for (int k = 0; k < 8; k++) v += al[k]*Cmat[k*512 + e];
            if (s <= 127) out[OFF_CL + ((size_t)b*TT + s)*512 + e] = v;
            else          g_C128[b*512 + e] = v;
        }
    }
}

// ============ main Kalman kernel ============
__global__ __launch_bounds__(256, 2)
void kf_kernel(const float* __restrict__ a_seq, float* __restrict__ out)
{
    __shared__ __align__(16) float P[1152], Pf[1152], Xb[1152], As[1152], AsT[1152];
    __shared__ __align__(16) float CHd[2][1152];
    __shared__ __align__(16) float Cb[2][576], CtT[2][640], CP[576], Wb[576], SG[320];
    __shared__ __align__(16) float zn[32], zfn[32], rvec[16], srv[16];

    const int tid = threadIdx.x, wid = tid >> 5, lane = tid & 31;
    const int b = blockIdx.x;

    if (tid < 32) zn[tid] = 0.f;
    #pragma unroll
    for (int k = 0; k < 4; k++){
        int e = tid + 256*k, i = e >> 5, j = e & 31;
        P[i*36 + j] = (i == j) ? 10.f : 0.f;
    }
    if (tid < 128){
        int e = tid*4, i = e >> 5, j = e & 31;
        float4 g = *(const float4*)(out + OFF_CL + (size_t)b*TT*512 + e);
        *(float4*)&Cb[0][i*36 + j] = g;
        CtT[0][(j+0)*20+i] = g.x; CtT[0][(j+1)*20+i] = g.y;
        CtT[0][(j+2)*20+i] = g.z; CtT[0][(j+3)*20+i] = g.w;
    }
    __syncthreads();

    if (wid < 6){
        for (int t = 0; t < TT; t++){
            const size_t bt = (size_t)b*TT + t;
            float* Ct = Cb[t&1];  float* Cn = Cb[(t+1)&1];
            float* CtTc = CtT[t&1]; float* CtTn = CtT[(t+1)&1];
            float* CHc = CHd[t&1];

            // phA: CP = C_t * P (128) || prefetch A_{t+1}, C_{t+1} + transposes (64)
            if (tid < 128){
                int i = tid >> 3, j4 = (tid & 7)*4;
                float4 a0 = make_float4(0,0,0,0), a1 = a0;
                #pragma unroll
                for (int m = 0; m < 16; m++){
                    float c0 = Ct[i*36 + m], c1 = Ct[i*36 + m + 16];
                    float4 p0 = *(const float4*)(P + m*36 + j4);
                    float4 p1 = *(const float4*)(P + (m+16)*36 + j4);
                    a0.x += c0*p0.x; a0.y += c0*p0.y; a0.z += c0*p0.z; a0.w += c0*p0.w;
                    a1.x += c1*p1.x; a1.y += c1*p1.y; a1.z += c1*p1.z; a1.w += c1*p1.w;
                }
                a0.x += a1.x; a0.y += a1.y; a0.z += a1.z; a0.w += a1.w;
                *(float4*)&CP[i*36 + j4] = a0;
            } else {
                int idx = tid - 128;
                #pragma unroll
                for (int r = 0; r < 6; r++){
                    int n4 = idx + 64*r;
                    if (n4 < 256){
                        int e = n4*4, i = e >> 5, j = e & 31;
                        float4 g = *(const float4*)(out + OFF_AL + bt*1024 + e);
                        *(float4*)&As[i*36 + j] = g;
                        AsT[(j+0)*36+i] = g.x; AsT[(j+1)*36+i] = g.y;
                        AsT[(j+2)*36+i] = g.z; AsT[(j+3)*36+i] = g.w;
                    } else {
                        int e = (n4 - 256)*4, i = e >> 5, j = e & 31;
                        float4 g = (t < 127) ? *(const float4*)(out + OFF_CL + (bt+1)*512 + e)
                                             : *(const float4*)(g_C128 + b*512 + e);
                        *(float4*)&Cn[i*36 + j] = g;
                        CtTn[(j+0)*20+i] = g.x; CtTn[(j+1)*20+i] = g.y;
                        CtTn[(j+2)*20+i] = g.z; CtTn[(j+3)*20+i] = g.w;
                    }
                }
            }
            BAR1;

            // phB: S = CP*Ct^T + 0.3I ; rvec
            if (tid < 64){
                int i = tid >> 2, j4 = (tid & 3)*4;
                float4 a0 = make_float4(0,0,0,0), a1 = a0;
                #pragma unroll
                for (int m = 0; m < 16; m++){
                    float c0 = CP[i*36 + m], c1 = CP[i*36 + m + 16];
                    float4 t0 = *(const float4*)(CtTc + m*20 + j4);
                    float4 t1 = *(const float4*)(CtTc + (m+16)*20 + j4);
                    a0.x += c0*t0.x; a0.y += c0*t0.y; a0.z += c0*t0.z; a0.w += c0*t0.w;
                    a1.x += c1*t1.x; a1.y += c1*t1.y; a1.z += c1*t1.z; a1.w += c1*t1.w;
                }
                a0.x += a1.x; a0.y += a1.y; a0.z += a1.z; a0.w += a1.w;
                if (j4+0 == i) a0.x += 0.3f;
                if (j4+1 == i) a0.y += 0.3f;
                if (j4+2 == i) a0.z += 0.3f;
                if (j4+3 == i) a0.w += 0.3f;
                *(float4*)&SG[i*20 + j4] = a0;
                *(float4*)(out + OFF_S + bt*256 + i*16 + j4) = a0;
            } else if (tid < 80){
                int la = tid - 64;
                float av = a_seq[bt*16 + la];
                rvec[la] = av - dot32(Ct + la*36, zn);
            }
            BAR2;

            // phC: deferred PF/PP stores of t-1 (warp7 runs GJ now)
            if (t > 0){
                const size_t bp = bt - 1;
                #pragma unroll
                for (int k = 0; k < 2; k++){
                    int n4 = tid + 192*k;
                    if (n4 < 256){
                        int e = n4*4, i = e >> 5, j = e & 31;
                        *(float4*)(out + OFF_PF + bp*1024 + e) = *(const float4*)&Pf[i*36 + j];
                        *(float4*)(out + OFF_PP + bp*1024 + e) = *(const float4*)&P[i*36 + j];
                    }
                }
            }
            BAR2;

            // phE: X = CP^T * W  (lower blocks only) ; zfn
            if (tid < 144){
                int i, j4; low_map(tid, i, j4);
                float4 a0 = make_float4(0,0,0,0), a1 = a0;
                #pragma unroll
                for (int m = 0; m < 8; m++){
                    float c0 = CP[m*36 + i], c1 = CP[(m+8)*36 + i];
                    float4 w0 = *(const float4*)(Wb + m*36 + j4);
                    float4 w1 = *(const float4*)(Wb + (m+8)*36 + j4);
                    a0.x += c0*w0.x; a0.y += c0*w0.y; a0.z += c0*w0.z; a0.w += c0*w0.w;
                    a1.x += c1*w1.x; a1.y += c1*w1.y; a1.z += c1*w1.z; a1.w += c1*w1.w;
                }
                a0.x += a1.x; a0.y += a1.y; a0.z += a1.z; a0.w += a1.w;
                *(float4*)&Xb[i*36 + j4] = a0;
            } else if (tid >= 160){
                int la = tid - 160;
                float s0 = zn[la], s1 = 0.f;
                #pragma unroll
                for (int m = 0; m < 8; m++){
                    s0 += CP[m*36 + la]*srv[m];
                    s1 += CP[(m+8)*36 + la]*srv[m+8];
                }
                zfn[la] = s0 + s1;
            }
            BAR1;

            // phF: Pf = P - X (X symmetric; mirror upper); CH = Pf + jitter; vec outputs
            #pragma unroll
            for (int r = 0; r < 2; r++){
                int T = tid + 192*r;
                if (T < 256){
                    int i = T >> 3, j4 = (T & 7)*4;
                    float4 p4 = *(const float4*)&P[i*36 + j4];
                    float4 x4;
                    if (j4 <= i) x4 = *(const float4*)&Xb[i*36 + j4];
                    else { x4.x = Xb[(j4+0)*36+i]; x4.y = Xb[(j4+1)*36+i];
                           x4.z = Xb[(j4+2)*36+i]; x4.w = Xb[(j4+3)*36+i]; }
                    float4 pf4 = make_float4(p4.x-x4.x, p4.y-x4.y, p4.z-x4.z, p4.w-x4.w);
                    *(float4*)&Pf[i*36 + j4] = pf4;
                    if (j4+0 == i) pf4.x += 2e-4f;
                    if (j4+1 == i) pf4.y += 2e-4f;
                    if (j4+2 == i) pf4.z += 2e-4f;
                    if (j4+3 == i) pf4.w += 2e-4f;
                    *(float4*)&CHc[i*36 + j4] = pf4;
                }
            }
            if (tid >= 64 && tid < 96){
                int la = tid - 64;
                float zp = dot32(As + la*36, zfn);
                zn[la] = zp;
                out[OFF_ZP + bt*32 + la] = zp;
            } else if (tid >= 96 && tid < 112){
                int la = tid - 96;
                out[OFF_AF + bt*16 + la] = dot32(Ct + la*36, zfn);
            } else if (tid >= 112 && tid < 144){
                int la = tid - 112;
                float z = zfn[la];
                out[OFF_ZF + bt*32 + la] = z;
                out[OFF_ZM + bt*32 + la] = z;
            }
            BAR3;

            // phG: M2 = A_{t+1} * Pf  (into Xb, full)
            #pragma unroll
            for (int r = 0; r < 2; r++){
                int T = tid + 192*r;
                if (T < 256){
                    int i = T >> 3, j4 = (T & 7)*4;
                    float4 a0 = make_float4(0,0,0,0), a1 = a0;
                    #pragma unroll
                    for (int m = 0; m < 16; m++){
                        float c0 = As[i*36 + m], c1 = As[i*36 + m + 16];
                        float4 p0 = *(const float4*)(Pf + m*36 + j4);
                        float4 p1 = *(const float4*)(Pf + (m+16)*36 + j4);
                        a0.x += c0*p0.x; a0.y += c0*p0.y; a0.z += c0*p0.z; a0.w += c0*p0.w;
                        a1.x += c1*p1.x; a1.y += c1*p1.y; a1.z += c1*p1.z; a1.w += c1*p1.w;
                    }
                    a0.x += a1.x; a0.y += a1.y; a0.z += a1.z; a0.w += a1.w;
                    *(float4*)&Xb[i*36 + j4] = a0;
                }
            }
            BAR1;

            // phH: RAW = M2 * A^T (symmetric; lower blocks, into As) ; a_pred
            if (tid < 144){
                int i, j4; low_map(tid, i, j4);
                float4 a0 = make_float4(0,0,0,0), a1 = a0;
                #pragma unroll
                for (int m = 0; m < 16; m++){
                    float c0 = Xb[i*36 + m], c1 = Xb[i*36 + m + 16];
                    float4 t0 = *(const float4*)(AsT + m*36 + j4);
                    float4 t1 = *(const float4*)(AsT + (m+16)*36 + j4);
                    a0.x += c0*t0.x; a0.y += c0*t0.y; a0.z += c0*t0.z; a0.w += c0*t0.w;
                    a1.x += c1*t1.x; a1.y += c1*t1.y; a1.z += c1*t1.z; a1.w += c1*t1.w;
                }
                a0.x += a1.x; a0.y += a1.y; a0.z += a1.z; a0.w += a1.w;
                *(float4*)&As[i*36 + j4] = a0;
            } else if (tid >= 160 && tid < 176){
                int la = tid - 160;
                out[OFF_AP + bt*16 + la] = dot32(Cn + la*36, zn);
            }
            BAR1;

            // phI: P = RAW (mirrored) + Q
            #pragma unroll
            for (int k = 0; k < 6; k++){
                int e = tid + 192*k;
                if (e < 1024){
                    int i = e >> 5, j = e & 31;
                    float v = (j <= i) ? As[i*36 + j] : As[j*36 + i];
                    P[i*36 + j] = v + ((i == j) ? 0.2f : 0.f);
                }
            }
            BAR1;
        }
    } else if (wid == 6){
        // ===== warp 6: register Cholesky, stores L directly =====
        for (int t = 0; t < TT; t++){
            BAR3;
            const float* CHc = CHd[t&1];
            float a[32];
            #pragma unroll
            for (int c = 0; c < 8; c++){
                float4 v = *(const float4*)(CHc + lane*36 + c*4);
                a[c*4] = v.x; a[c*4+1] = v.y; a[c*4+2] = v.z; a[c*4+3] = v.w;
            }
            float* o = out + OFF_LT + ((size_t)b*TT + t)*1024 + lane*32;
            #pragma unroll
            for (int j = 0; j < 32; j++){
                float d = __shfl_sync(0xffffffffu, a[j], j);
                float lij = a[j] * rsqrtf(d);
                o[j] = (lane >= j) ? lij : 0.f;
                #pragma unroll
                for (int k = j+1; k < 32; k++)
                    a[k] -= lij * __shfl_sync(0xffffffffu, lij, k);
            }
        }
    } else {
        // ===== warp 7: GJ on [S | r | CP] -> Wb = Sinv*CP, srv = Sinv*r =====
        for (int t = 0; t < TT; t++){
            BAR2;
            float c[16], d[16];
            #pragma unroll
            for (int i = 0; i < 16; i++){
                c[i] = (lane < 16) ? SG[i*20 + lane] : ((lane == 16) ? rvec[i] : 0.f);
                d[i] = CP[i*36 + lane];
            }
            #pragma unroll
            for (int p = 0; p < 16; p++){
                float piv = __shfl_sync(0xffffffffu, c[p], p);
                float inv = 1.0f/piv;
                float pc = c[p]*inv, pd = d[p]*inv;
                #pragma unroll
                for (int i = 0; i < 16; i++){
                    if (i == p) continue;
                    float fc = __shfl_sync(0xffffffffu, c[i], p);
                    c[i] -= fc*pc; d[i] -= fc*pd;
                }
                c[p] = pc; d[p] = pd;
            }
            #pragma unroll
            for (int i = 0; i < 16; i++) Wb[i*36 + lane] = d[i];
            if (lane == 16){
                #pragma unroll
                for (int i = 0; i < 16; i++) srv[i] = c[i];
            }
            BAR2;
        }
    }

    __syncthreads();
    // epilogue: PF/PP for t = 127
    const size_t bl = (size_t)b*TT + 127;
    if (tid < 256){
        #pragma unroll
        for (int k = 0; k < 1; k++){
            int n4 = tid;
            if (n4 < 256){
                int e = n4*4, i = e >> 5, j = e & 31;
                *(float4*)(out + OFF_PF + bl*1024 + e) = *(const float4*)&Pf[i*36 + j];
                *(float4*)(out + OFF_PP + bl*1024 + e) = *(const float4*)&P[i*36 + j];
            }
        }
    }
}

extern "C" void kernel_launch(void* const* d_in, const int* in_sizes, int n_in,
                              void* d_out, int out_size) {
    const float* a_seq = (const float*)d_in[0];
    const float* h_obs = (const float*)d_in[1];
    const float* Amat  = (const float*)d_in[2];
    const float* Cmat  = (const float*)d_in[3];
    const float* a0    = (const float*)d_in[4];
    const float* Wx    = (const float*)d_in[5];
    const float* Wh    = (const float*)d_in[6];
    const float* bb    = (const float*)d_in[7];
    const float* Wo    = (const float*)d_in[8];
    const float* bo    = (const float*)d_in[9];
    float* out = (float*)d_out;

    gru_kernel<<<NB, 192>>>(a_seq, h_obs, a0, Wx, Wh, bb, Wo, bo, out);
    mix_kernel<<<dim3(NB, 129), 192>>>(Amat, Cmat, out);
    kf_kernel<<<NB, 256>>>(a_seq, out);
}